// round 11
// baseline (speedup 1.0000x reference)
#include <cuda_runtime.h>
#include <cuda_bf16.h>
#include <math.h>

#define B 64
#define C 256
#define D 128
#define KTOP 8
#define G2 296
#define TILE 128
#define MAXN 100352              // 784 * 128, >= N
#define NCAND (G2*KTOP)          // 2368
#define M1 16                    // exact-rescore window
#define KW 68                    // bf16 row stride in 32-bit words (68%32=4 -> conflict-free)
#define SIM_LD 132               // sims fp32 row stride

// smem layout in 32-bit words (sim kernel)
#define OFF_QW   0               // Q bf16: 64 x 68 = 4352
#define OFF_K0   4352            // K bf16 buf0: 128 x 68 = 8704
#define OFF_K1   13056           // K bf16 buf1
#define OFF_SCL  21760           // scale fp32: 2 x 128
#define SMEM_WORDS 22016         // 88064 B -> 2 CTAs/SM

#define QPROJ_BLOCKS 512
#define CONV_BLOCKS  (MAXN/64)   // 1568 blocks x 64 keys

// scratch (device globals: no allocations allowed)
__device__ __align__(16) __nv_bfloat16 g_kbf[MAXN*D];  // keys in bf16
__device__ __align__(16) float g_scale[MAXN];          // imp/||k|| (exact fp32)
__device__ float g_qRow[B*D];        // q (unnormalized) row-major [b][d]
__device__ float g_cval[B*NCAND];    // per-block top-8 values
__device__ int   g_cidx[B*NCAND];    // per-block top-8 indices

__device__ __forceinline__ float warpsum(float v) {
    v += __shfl_xor_sync(0xffffffff, v, 16);
    v += __shfl_xor_sync(0xffffffff, v, 8);
    v += __shfl_xor_sync(0xffffffff, v, 4);
    v += __shfl_xor_sync(0xffffffff, v, 2);
    v += __shfl_xor_sync(0xffffffff, v, 1);
    return v;
}

// bf16x2 pack: w = {hi: cvt(h), lo: cvt(l)}
#define CVT2(w, h, l) \
    asm("cvt.rn.bf16x2.f32 %0, %1, %2;" : "=r"(w) : "f"(h), "f"(l))

// m16n8k16 bf16 MMA, fp32 accumulate
#define MMA_BF16(d0,d1,d2,d3, a0,a1,a2,a3, b0,b1) \
    asm("mma.sync.aligned.m16n8k16.row.col.f32.bf16.bf16.f32 " \
        "{%0,%1,%2,%3}, {%4,%5,%6,%7}, {%8,%9}, {%0,%1,%2,%3};" \
        : "+f"(d0), "+f"(d1), "+f"(d2), "+f"(d3) \
        : "r"(a0), "r"(a1), "r"(a2), "r"(a3), "r"(b0), "r"(b1))

// 16B async copy global -> shared
__device__ __forceinline__ void cp16(unsigned dst, const void* src) {
    asm volatile("cp.async.cg.shared.global [%0], [%1], 16;" :: "r"(dst), "l"(src));
}
#define CP_COMMIT() asm volatile("cp.async.commit_group;")
#define CP_WAIT0()  asm volatile("cp.async.wait_group 0;")

// ---------------------------------------------------------------------------
// Kernel 1 (fused prep):
//   blocks [0, QPROJ_BLOCKS):  q = query @ W_q^T + b_q  (no normalization)
//   blocks [QPROJ_BLOCKS, +CONV_BLOCKS): keys fp32->bf16 + scale = imp/||k||
// ---------------------------------------------------------------------------
__global__ void prep_kernel(const float* __restrict__ query,
                            const float* __restrict__ Wq,
                            const float* __restrict__ bq,
                            const float* __restrict__ keys,
                            const float* __restrict__ importance,
                            int N) {
    const int lane = threadIdx.x & 31;
    if (blockIdx.x < QPROJ_BLOCKS) {
        // ---- q projection: 4096 warps, 2 outputs each
        const int gw = (blockIdx.x * blockDim.x + threadIdx.x) >> 5;  // 0..4095
        const int b  = gw >> 6;
        const int d0 = (gw & 63) << 1;

        const float* qr = query + (size_t)b * C;
        const float* w0 = Wq + (size_t)(d0 + 0) * C;
        const float* w1 = Wq + (size_t)(d0 + 1) * C;

        float a0 = 0.f, a1 = 0.f;
        #pragma unroll
        for (int j = 0; j < 8; j++) {
            int c = lane + 32 * j;
            float q = __ldg(qr + c);
            a0 += q * __ldg(w0 + c);
            a1 += q * __ldg(w1 + c);
        }
        #pragma unroll
        for (int off = 16; off; off >>= 1) {
            a0 += __shfl_xor_sync(0xffffffff, a0, off);
            a1 += __shfl_xor_sync(0xffffffff, a1, off);
        }
        if (lane == 0) {
            g_qRow[b*D + d0 + 0] = a0 + bq[d0 + 0];
            g_qRow[b*D + d0 + 1] = a1 + bq[d0 + 1];
        }
    } else {
        // ---- key conversion + exact scale; 64 keys per block, 8 per warp
        const int cb   = blockIdx.x - QPROJ_BLOCKS;
        const int wid  = threadIdx.x >> 5;
        const int base = cb * 64 + wid * 8;
        #pragma unroll
        for (int i = 0; i < 8; i++) {
            int n = base + i;
            float4 v = make_float4(0.f, 0.f, 0.f, 0.f);
            if (n < N)
                v = reinterpret_cast<const float4*>(keys)[(size_t)n*32 + lane];
            float ssq = warpsum(v.x*v.x + v.y*v.y + v.z*v.z + v.w*v.w);
            unsigned wlo, whi;
            CVT2(wlo, v.y, v.x);
            CVT2(whi, v.w, v.z);
            reinterpret_cast<uint2*>(g_kbf)[(size_t)n*32 + lane] = make_uint2(wlo, whi);
            if (lane == 0) {
                float imp = (n < N) ? importance[n] : 0.f;
                g_scale[n] = imp / fmaxf(sqrtf(ssq), 1e-12f);
            }
        }
    }
}

// ---------------------------------------------------------------------------
// Kernel 2: 64x128 sim tile via bf16 m16n8k16 MMA, cp.async double-buffered
// bf16 key tiles (pre-converted), 2 CTAs/SM resident, running top-8 per row.
// ---------------------------------------------------------------------------
__global__ void __launch_bounds__(256, 2)
sim_topk_kernel(int N) {
    extern __shared__ unsigned smw[];          // word-addressed smem
    unsigned* Qw = smw + OFF_QW;
    const unsigned sbase = (unsigned)__cvta_generic_to_shared(smw);

    const int tid = threadIdx.x;               // 256 threads
    const int g   = blockIdx.x;
    const int wid = tid >> 5, lane = tid & 31;
    const int wm  = wid & 1,  wn  = wid >> 1;  // MMA warp grid 2x4
    const int gid = lane >> 2, tig = lane & 3; // fragment coords
    const int rr  = tid >> 2, ss = tid & 3;    // scan: 4 scanners per row

    // --- resident Q in bf16 natural layout [m][k]
    {
        const float4* qsrc = (const float4*)g_qRow;
        #pragma unroll
        for (int i = 0; i < 8; i++) {
            int r = wid + 8*i;                 // 0..63
            float4 v = qsrc[r*32 + lane];
            unsigned wlo, whi;
            CVT2(wlo, v.y, v.x);
            CVT2(whi, v.w, v.z);
            *reinterpret_cast<uint2*>(Qw + r*KW + lane*2) = make_uint2(wlo, whi);
        }
    }

    // running top-8 per (row, col-slice) stream
    float tv[KTOP]; int tix[KTOP];
    #pragma unroll
    for (int k = 0; k < KTOP; k++) { tv[k] = -INFINITY; tix[k] = 0; }
    float vmin = -INFINITY; int minpos = 0;

    const int T = (N + TILE - 1) / TILE;

    // --- async tile loader: 128 rows x 256B, 8 x 16B chunks per thread
    const int lrow = tid >> 1, lhalf = tid & 1;
    auto loadK_async = [&](int t, int buf) {
        int base = t * TILE;
        const char* src = (const char*)(g_kbf + (size_t)(base + lrow)*D + lhalf*64);
        unsigned dst = sbase + (buf ? OFF_K1 : OFF_K0)*4 + lrow*(KW*4) + lhalf*128;
        #pragma unroll
        for (int j = 0; j < 8; j++) cp16(dst + j*16, src + j*16);
        if (tid < 32)
            cp16(sbase + (OFF_SCL + buf*128)*4 + tid*16,
                 (const char*)(g_scale + base) + tid*16);
        CP_COMMIT();
    };

    if (g < T) loadK_async(g, 0);
    int cur = 0;

    for (int tc = g; tc < T; tc += G2, cur ^= 1) {
        const int base = tc * TILE;
        unsigned* Kw = smw + (cur ? OFF_K1 : OFF_K0);
        float* scl = (float*)(smw + OFF_SCL + cur*128);

        CP_WAIT0();
        __syncthreads();   // K[cur]+scl[cur] landed; Q ready; prev scan done

        const int tn = tc + G2;
        if (tn < T) loadK_async(tn, cur ^ 1);   // non-blocking; overlaps MMA

        // --- MMA: 2 M-tiles x 4 N-strips x 8 k16-steps, natural layouts
        float acc[2][4][4];
        #pragma unroll
        for (int mt = 0; mt < 2; mt++)
            #pragma unroll
            for (int sn = 0; sn < 4; sn++)
                #pragma unroll
                for (int r = 0; r < 4; r++) acc[mt][sn][r] = 0.f;

        const int bm = 32*wm, bn = 32*wn;
        #pragma unroll
        for (int wk0 = 0; wk0 < 64; wk0 += 8) {      // word k-offset
            unsigned a[2][4], b[4][2];
            #pragma unroll
            for (int mt = 0; mt < 2; mt++) {
                const unsigned* qa = Qw + (bm + 16*mt + gid)*KW + wk0 + tig;
                a[mt][0] = qa[0];
                a[mt][1] = qa[8*KW];
                a[mt][2] = qa[4];
                a[mt][3] = qa[8*KW + 4];
            }
            #pragma unroll
            for (int sn = 0; sn < 4; sn++) {
                const unsigned* kb = Kw + (bn + 8*sn + gid)*KW + wk0 + tig;
                b[sn][0] = kb[0];
                b[sn][1] = kb[4];
            }
            #pragma unroll
            for (int mt = 0; mt < 2; mt++)
                #pragma unroll
                for (int sn = 0; sn < 4; sn++)
                    MMA_BF16(acc[mt][sn][0], acc[mt][sn][1], acc[mt][sn][2], acc[mt][sn][3],
                             a[mt][0], a[mt][1], a[mt][2], a[mt][3],
                             b[sn][0], b[sn][1]);
        }

        __syncthreads();   // MMA reads of K[cur] done -> safe to overwrite with sims

        // --- scaled sims into K[cur] region as fp32 [64][SIM_LD]
        float* simsF = (float*)Kw;
        #pragma unroll
        for (int mt = 0; mt < 2; mt++) {
            int r0 = bm + 16*mt + gid;
            #pragma unroll
            for (int sn = 0; sn < 4; sn++) {
                int c0 = bn + 8*sn + 2*tig;
                float s0 = scl[c0], s1 = scl[c0+1];
                simsF[r0*SIM_LD + c0]         = acc[mt][sn][0] * s0;
                simsF[r0*SIM_LD + c0 + 1]     = acc[mt][sn][1] * s1;
                simsF[(r0+8)*SIM_LD + c0]     = acc[mt][sn][2] * s0;
                simsF[(r0+8)*SIM_LD + c0 + 1] = acc[mt][sn][3] * s1;
            }
        }
        __syncthreads();   // sims visible

        // --- running top-8: scanner ss takes cols ss, ss+4, ... (conflict-free)
        {
            int nmax = N - base; if (nmax > TILE) nmax = TILE;
            int cnt = (nmax > ss) ? ((nmax - ss + 3) >> 2) : 0;
            const float* sr = (const float*)Kw + rr*SIM_LD + ss;
            for (int n = 0; n < cnt; n++) {
                float v = sr[4*n];
                if (v > vmin) {
                    tv[minpos] = v; tix[minpos] = base + 4*n + ss;
                    vmin = tv[0]; minpos = 0;
                    #pragma unroll
                    for (int k = 1; k < KTOP; k++)
                        if (tv[k] < vmin) { vmin = tv[k]; minpos = k; }
                }
            }
        }
        // next iteration's top sync orders this scan before any reuse of K[cur]
    }

    // --- merge 4 scanner streams per row -> 8 candidates per row
    __syncthreads();
    float* bufv = (float*)(smw + OFF_QW);          // alias Q region (done)
    int*   bufi = (int*)(smw + OFF_QW + 2048);
    #pragma unroll
    for (int k = 0; k < KTOP; k++) { bufv[tid*KTOP + k] = tv[k]; bufi[tid*KTOP + k] = tix[k]; }
    __syncthreads();
    if (tid < 64) {
        float fv[KTOP]; int fi[KTOP];
        #pragma unroll
        for (int k = 0; k < KTOP; k++) { fv[k] = -INFINITY; fi[k] = 0; }
        float fmin = -INFINITY; int fpos = 0;
        int e0 = (4*tid)*KTOP;
        for (int e = 0; e < 4*KTOP; e++) {
            float v = bufv[e0 + e];
            if (v > fmin) {
                fv[fpos] = v; fi[fpos] = bufi[e0 + e];
                fmin = fv[0]; fpos = 0;
                #pragma unroll
                for (int k = 1; k < KTOP; k++)
                    if (fv[k] < fmin) { fmin = fv[k]; fpos = k; }
            }
        }
        int o = tid*NCAND + g*KTOP;
        #pragma unroll
        for (int k = 0; k < KTOP; k++) { g_cval[o+k] = fv[k]; g_cidx[o+k] = fi[k]; }
    }
}

// ---------------------------------------------------------------------------
// Kernel 3: merge candidates -> approx top-M1 -> EXACT fp32 rescore -> top-8,
// gather values, softmax attention, combine, out = mem @ W_comb^T + b_comb
// ---------------------------------------------------------------------------
__global__ void final_kernel(const float* __restrict__ keys,
                             const float* __restrict__ values,
                             const float* __restrict__ importance,
                             const float* __restrict__ w_attn,
                             const float* __restrict__ b_attn,
                             const float* __restrict__ Wcomb,
                             const float* __restrict__ bcomb,
                             float* __restrict__ out,
                             int N) {
    __shared__ float cv[NCAND];
    __shared__ int   ci[NCAND];
    __shared__ float rv[8];
    __shared__ int   rp[8];
    __shared__ int   candIdx[M1];
    __shared__ float rs[M1];
    __shared__ float qrow[D];
    __shared__ int   topidx[KTOP];
    __shared__ float vs[KTOP*129];
    __shared__ float wa[D];
    __shared__ float ts[KTOP];
    __shared__ float sc[KTOP];
    __shared__ float ms[D];

    const int b = blockIdx.x;
    const int tid = threadIdx.x;          // 256 threads
    const int wid = tid >> 5, lane = tid & 31;

    for (int i = tid; i < NCAND; i += 256) {
        cv[i] = g_cval[b*NCAND + i];
        ci[i] = g_cidx[b*NCAND + i];
    }
    if (tid < D) { wa[tid] = w_attn[tid]; qrow[tid] = g_qRow[b*D + tid]; }
    __syncthreads();

    // M1 rounds of argmax (warp-shuffle reduce, 2 syncs/round)
    for (int k = 0; k < M1; k++) {
        float best = -INFINITY; int bp = 0;
        for (int i = tid; i < NCAND; i += 256)
            if (cv[i] > best) { best = cv[i]; bp = i; }
        #pragma unroll
        for (int off = 16; off; off >>= 1) {
            float ov = __shfl_xor_sync(0xffffffff, best, off);
            int   oi = __shfl_xor_sync(0xffffffff, bp, off);
            if (ov > best) { best = ov; bp = oi; }
        }
        if (lane == 0) { rv[wid] = best; rp[wid] = bp; }
        __syncthreads();
        if (tid == 0) {
            float bb = rv[0]; int bi = rp[0];
            #pragma unroll
            for (int w = 1; w < 8; w++)
                if (rv[w] > bb) { bb = rv[w]; bi = rp[w]; }
            candIdx[k] = ci[bi];
            cv[bi] = -INFINITY;
        }
        __syncthreads();
    }

    // EXACT fp32 rescore of the M1 candidates (one warp per candidate)
    for (int j = wid; j < M1; j += 8) {
        int idx = candIdx[j];
        idx = idx < 0 ? 0 : (idx >= N ? N-1 : idx);
        const float4* kr = reinterpret_cast<const float4*>(keys + (size_t)idx * D);
        float4 k4 = kr[lane];
        float4 q4 = *reinterpret_cast<const float4*>(qrow + 4*lane);
        float dot = q4.x*k4.x + q4.y*k4.y + q4.z*k4.z + q4.w*k4.w;
        float ssq = k4.x*k4.x + k4.y*k4.y + k4.z*k4.z + k4.w*k4.w;
        dot = warpsum(dot);
        ssq = warpsum(ssq);
        if (lane == 0)
            rs[j] = importance[idx] * dot / fmaxf(sqrtf(ssq), 1e-12f);
    }
    __syncthreads();

    // exact top-8 of the M1 rescored candidates
    if (tid == 0) {
        #pragma unroll
        for (int k = 0; k < KTOP; k++) {
            float best = -INFINITY; int bp = 0;
            for (int j = 0; j < M1; j++)
                if (rs[j] > best) { best = rs[j]; bp = j; }
            topidx[k] = candIdx[bp];
            rs[bp] = -INFINITY;
        }
    }
    __syncthreads();

    // gather retrieved values
    if (tid < D) {
        #pragma unroll
        for (int k = 0; k < KTOP; k++)
            vs[k*129 + tid] = values[(size_t)topidx[k]*D + tid];
    }
    __syncthreads();

    // attention logits
    if (tid < KTOP) {
        float acc = b_attn[0];
        for (int d = 0; d < D; d++) acc += vs[tid*129 + d] * wa[d];
        ts[tid] = acc;
    }
    __syncthreads();
    if (tid == 0) {
        float mx = ts[0];
        #pragma unroll
        for (int k = 1; k < KTOP; k++) mx = fmaxf(mx, ts[k]);
        float e[KTOP]; float s = 0.f;
        #pragma unroll
        for (int k = 0; k < KTOP; k++) { e[k] = expf(ts[k] - mx); s += e[k]; }
        #pragma unroll
        for (int k = 0; k < KTOP; k++) sc[k] = e[k] / s;
    }
    __syncthreads();

    // weighted memory
    if (tid < D) {
        float mm = 0.f;
        #pragma unroll
        for (int k = 0; k < KTOP; k++) mm += sc[k] * vs[k*129 + tid];
        ms[tid] = mm;
    }
    __syncthreads();

    // out = mem @ W_comb^T + b_comb  (warp-coalesced matvec)
    for (int d = wid; d < D; d += 8) {
        const float* wr = Wcomb + (size_t)d*D;
        float acc = 0.f;
        #pragma unroll
        for (int j = 0; j < 4; j++) {
            int e = lane + 32*j;
            acc += ms[e] * wr[e];
        }
        acc = warpsum(acc);
        if (lane == 0) out[b*D + d] = acc + bcomb[d];
    }
}

// ---------------------------------------------------------------------------
extern "C" void kernel_launch(void* const* d_in, const int* in_sizes, int n_in,
                              void* d_out, int out_size) {
    const float* query      = (const float*)d_in[0];
    const float* keys       = (const float*)d_in[1];
    const float* values     = (const float*)d_in[2];
    const float* importance = (const float*)d_in[3];
    const float* Wq         = (const float*)d_in[4];
    const float* bq         = (const float*)d_in[5];
    const float* w_attn     = (const float*)d_in[6];
    const float* b_attn     = (const float*)d_in[7];
    const float* Wcomb      = (const float*)d_in[8];
    const float* bcomb      = (const float*)d_in[9];
    const int N = in_sizes[1] / D;

    const size_t smem2_bytes = (size_t)SMEM_WORDS * 4;
    cudaFuncSetAttribute(sim_topk_kernel,
                         cudaFuncAttributeMaxDynamicSharedMemorySize, (int)smem2_bytes);

    prep_kernel<<<QPROJ_BLOCKS + CONV_BLOCKS, 256>>>(query, Wq, bq, keys, importance, N);
    sim_topk_kernel<<<G2, 256, smem2_bytes>>>(N);
    final_kernel<<<B, 256>>>(keys, values, importance, w_attn, b_attn,
                             Wcomb, bcomb, (float*)d_out, N);
}